// round 7
// baseline (speedup 1.0000x reference)
#include <cuda_runtime.h>

// Problem constants
#define T_STEPS 2048
#define B_TOT   256
#define H_DIM   512
#define D_IN    529            // 16 (x) + 512 (h) + 1 (cost)
#define KPAD    560            // padded K: 10 slices * 56
#define STRIDE  560            // in_s row stride (floats)
#define SLICE   56             // floats per j-slice (14 x float4)
#define JS      10             // j-slices
#define NW      140            // 16B words per inter row
#define CTAS_PER_CL 8
#define B_PER_CL    16
#define ROWS_PER_CTA 64
#define NTHREADS 640           // 20 warps = 2 rowgroups x 10 j-slices
#define XROW    20             // xc staging row: 16 x + 1 cost + pad

// ping-pong hidden-state buffers (L2 resident, 2MB total)
__device__ float g_hbuf[2][B_TOT * H_DIM];

__device__ __forceinline__ void ffma2(unsigned long long &d, unsigned long long a, unsigned long long b) {
    // packed dual fp32 FMA: d.lo += a.lo*b.lo ; d.hi += a.hi*b.hi
    asm("fma.rn.f32x2 %0, %1, %2, %0;" : "+l"(d) : "l"(a), "l"(b));
}

__device__ __forceinline__ float unpack_sum(unsigned long long v) {
    float lo = __uint_as_float((unsigned)(v & 0xffffffffull));
    float hi = __uint_as_float((unsigned)(v >> 32));
    return lo + hi;
}

__device__ __forceinline__ unsigned long long packf2(float lo, float hi) {
    return ((unsigned long long)__float_as_uint(hi) << 32) | (unsigned long long)__float_as_uint(lo);
}

extern "C" __global__ void __launch_bounds__(NTHREADS, 1) __cluster_dims__(CTAS_PER_CL, 1, 1)
rnn_scan_kernel(const float* __restrict__ x,       // [B, T, 16]
                const float* __restrict__ hidden,  // [B, 512]
                const float* __restrict__ cost,    // [B, T]
                const float* __restrict__ Wo,      // [1, 529]
                const float* __restrict__ Wh,      // [512, 529]
                float* __restrict__ out)           // [B*T] outs, then [B*512] h_final
{
    extern __shared__ float smem[];
    float* in_s = smem;                           // 16 x 560 : [x(16)|h(512)|c(1)|zeros(31)]
    float* Wo_s = in_s + B_PER_CL * STRIDE;       // 560
    float* red  = Wo_s + STRIDE;                  // JS x 16 x 64 partials = 10240 floats
    float* xc_s = red + JS * B_PER_CL * ROWS_PER_CTA;  // 2 x 16 x 20 double buffer

    const int tid   = threadIdx.x;
    const int lane  = tid & 31;
    const int w     = tid >> 5;                   // warp 0..19
    const int rg    = (w < JS) ? 0 : 1;           // rowgroup
    const int jc    = (w < JS) ? w : (w - JS);    // j-slice 0..9
    const int r_loc = rg * 32 + lane;             // local output row 0..63

    const int crank = blockIdx.x & (CTAS_PER_CL - 1);
    const int clid  = blockIdx.x >> 3;
    const int bbase = clid * B_PER_CL;
    const int row0  = crank * ROWS_PER_CTA;

    // ---- one-time: load my W slice into registers (zero-padded to 560 cols) ----
    unsigned long long Wr[SLICE / 2];
    {
        const float* wrow = Wh + (size_t)(row0 + r_loc) * D_IN;
        #pragma unroll
        for (int k = 0; k < SLICE / 2; ++k) {
            int c0 = jc * SLICE + 2 * k;
            float lo = (c0     < D_IN) ? __ldg(wrow + c0)     : 0.0f;
            float hi = (c0 + 1 < D_IN) ? __ldg(wrow + c0 + 1) : 0.0f;
            Wr[k] = packf2(lo, hi);
        }
    }

    // ---- one-time: Wo padded, in_s tail zeros, hidden -> g_hbuf[1], x/cost t=0 ----
    for (int idx = tid; idx < STRIDE; idx += NTHREADS)
        Wo_s[idx] = (idx < D_IN) ? Wo[idx] : 0.0f;
    for (int z = tid; z < B_PER_CL * (STRIDE - D_IN); z += NTHREADS) {
        int b = z / (STRIDE - D_IN);
        int c = D_IN + (z - b * (STRIDE - D_IN));
        in_s[b * STRIDE + c] = 0.0f;
    }
    for (int idx = tid; idx < 2 * H_DIM; idx += NTHREADS) {
        int bl  = idx >> 9;
        int col = idx & (H_DIM - 1);
        size_t off = (size_t)(bbase + crank * 2 + bl) * H_DIM + col;
        g_hbuf[1][off] = hidden[off];
    }
    if (tid >= 512) {
        int t2 = tid - 512;                      // 0..127
        int b = t2 >> 3, q = t2 & 7;
        const float* xp = x + ((size_t)(bbase + b) * T_STEPS) * 16;
        xc_s[b * XROW + 2 * q]     = __ldg(xp + 2 * q);
        xc_s[b * XROW + 2 * q + 1] = __ldg(xp + 2 * q + 1);
        if (q == 0) xc_s[b * XROW + 16] = __ldg(cost + (size_t)(bbase + b) * T_STEPS);
    }
    __syncthreads();
    asm volatile("barrier.cluster.arrive.aligned;" ::: "memory");
    asm volatile("barrier.cluster.wait.aligned;"   ::: "memory");

    for (int t = 0; t < T_STEPS; ++t) {
        const int cur = t & 1;
        // ---- stage inter = [x_t | h | c_t] into in_s ----
        if (w < 16) {
            // warp w stages h of batch row w
            const float4* hsrc = (const float4*)(g_hbuf[(t + 1) & 1] + (size_t)(bbase + w) * H_DIM);
            float4* hdst = (float4*)(in_s + w * STRIDE + 16);
            #pragma unroll
            for (int k = 0; k < 4; ++k)
                hdst[k * 32 + lane] = __ldcg(hsrc + k * 32 + lane);
        } else {
            // warps 16-19 copy x/cost from xc_s staging buffer
            int t2 = tid - 512;
            for (int i = t2; i < B_PER_CL * 17; i += 128) {
                int b = i / 17, q = i - b * 17;
                int col = (q < 16) ? q : 528;
                in_s[b * STRIDE + col] = xc_s[cur * B_PER_CL * XROW + b * XROW + q];
            }
        }
        __syncthreads();

        // ---- prefetch x/cost for t+1 into the other xc buffer ----
        if (tid >= 512 && t + 1 < T_STEPS) {
            int t2 = tid - 512;
            int b = t2 >> 3, q = t2 & 7;
            float* dst = xc_s + ((t + 1) & 1) * B_PER_CL * XROW + b * XROW;
            const float* xp = x + ((size_t)(bbase + b) * T_STEPS + (t + 1)) * 16;
            dst[2 * q]     = __ldg(xp + 2 * q);
            dst[2 * q + 1] = __ldg(xp + 2 * q + 1);
            if (q == 0) dst[16] = __ldg(cost + (size_t)(bbase + b) * T_STEPS + (t + 1));
        }

        // ---- o_t = Wo . inter  (cluster CTA 0 only; in_s holds full inter) ----
        if (crank == 0 && w < 16) {
            int b = w;
            const ulonglong2* wop = (const ulonglong2*)Wo_s;
            const ulonglong2* hp  = (const ulonglong2*)(in_s + b * STRIDE);
            unsigned long long acc0 = 0ull;
            int w0 = lane * 5;
            int w1 = min(NW, w0 + 5);
            for (int q = w0; q < w1; ++q) {
                ulonglong2 a = wop[q], h = hp[q];
                ffma2(acc0, a.x, h.x);
                ffma2(acc0, a.y, h.y);
            }
            float r = unpack_sum(acc0);
            r += __shfl_xor_sync(0xffffffffu, r, 1);
            r += __shfl_xor_sync(0xffffffffu, r, 2);
            r += __shfl_xor_sync(0xffffffffu, r, 4);
            r += __shfl_xor_sync(0xffffffffu, r, 8);
            r += __shfl_xor_sync(0xffffffffu, r, 16);
            if (lane == 0) out[(size_t)(bbase + b) * T_STEPS + t] = r;
        }

        // ---- main matvec: W rows in regs (56), h broadcast from SMEM ----
        #pragma unroll
        for (int g = 0; g < 4; ++g) {
            unsigned long long acc[4];
            #pragma unroll
            for (int b = 0; b < 4; ++b) acc[b] = 0ull;

            const float* hbase = in_s + (g * 4) * STRIDE + jc * SLICE;
            #pragma unroll
            for (int kk = 0; kk < SLICE / 4; ++kk) {       // 14 x 16B chunks
                #pragma unroll
                for (int b = 0; b < 4; ++b) {
                    ulonglong2 hv = *(const ulonglong2*)(hbase + b * STRIDE + 4 * kk);
                    ffma2(acc[b], Wr[2 * kk],     hv.x);
                    ffma2(acc[b], Wr[2 * kk + 1], hv.y);
                }
            }
            #pragma unroll
            for (int b = 0; b < 4; ++b)
                red[(jc * 16 + g * 4 + b) * 64 + r_loc] = unpack_sum(acc[b]);
        }
        __syncthreads();

        // ---- reduce JS partials, write h_new ----
        {
            float* hdst = (t == T_STEPS - 1) ? (out + (size_t)B_TOT * T_STEPS)
                                             : g_hbuf[t & 1];
            for (int p = tid; p < B_PER_CL * ROWS_PER_CTA; p += NTHREADS) {
                float s = 0.0f;
                #pragma unroll
                for (int j = 0; j < JS; ++j) s += red[j * 1024 + p];
                int b = p >> 6, r = p & 63;
                __stcg(hdst + (size_t)(bbase + b) * H_DIM + row0 + r, s);
            }
        }

        // ---- cluster barrier: publish h_new before next step reads ----
        asm volatile("barrier.cluster.arrive.aligned;" ::: "memory");
        asm volatile("barrier.cluster.wait.aligned;"   ::: "memory");
    }
}

extern "C" void kernel_launch(void* const* d_in, const int* in_sizes, int n_in,
                              void* d_out, int out_size) {
    const float* x      = (const float*)d_in[0];
    const float* hidden = (const float*)d_in[1];
    const float* cost   = (const float*)d_in[2];
    const float* Wo     = (const float*)d_in[3];
    const float* Wh     = (const float*)d_in[4];
    float* out = (float*)d_out;

    size_t smem = (size_t)(B_PER_CL * STRIDE + STRIDE + JS * B_PER_CL * ROWS_PER_CTA
                           + 2 * B_PER_CL * XROW) * sizeof(float);
    cudaFuncSetAttribute(rnn_scan_kernel, cudaFuncAttributeMaxDynamicSharedMemorySize, (int)smem);
    rnn_scan_kernel<<<128, NTHREADS, smem>>>(x, hidden, cost, Wo, Wh, out);
}